// round 1
// baseline (speedup 1.0000x reference)
#include <cuda_runtime.h>
#include <cub/cub.cuh>
#include <stdint.h>

// ---------------- problem constants ----------------
#define HF 96
#define WF 96
#define NPOS (HF*WF)            // 9216
#define CIN 1024
#define COUT 512
#define NA 15
#define NANCH (NPOS*NA)         // 138240
#define PRE 6000
#define POST 300
#define NW 94                   // ceil(6000/64)
#define FEAT_ELEMS (1*1024*96*96)

// ---------------- device scratch (static, no allocs) ----------------
__device__ float g_w2[CIN*9*COUT];                 // conv1 weights transposed: [ic*9+kk][oc]
__device__ float g_Xt[(size_t)NPOS*COUT];          // conv1+BN+ReLU output, [pos][oc]
__device__ float g_wpad[COUT*96];                  // heads weights: [c][96] (30 cls, 60 bbox, 6 pad)
__device__ float g_dots[(size_t)NPOS*96];          // heads outputs per position
__device__ float g_box[(size_t)NANCH*4];           // clipped boxes per anchor
__device__ unsigned long long g_keys[NANCH];
__device__ unsigned long long g_keys_sorted[NANCH];
__device__ float g_bs[PRE*4];                      // top-6000 boxes (sorted)
__device__ float g_area[PRE];
__device__ int   g_valid[PRE];
__device__ unsigned long long g_mask[(size_t)PRE*NW];
__device__ unsigned char g_cub_temp[16u*1024u*1024u];

// anchors for base_size=16, ratios (0.5,1,2) x scales (2,4,8,16,32); exact in fp32
__constant__ float c_anchors[NA][4] = {
  {-15.f,  -4.f,  30.f,  19.f}, { -38.f, -16.f,  53.f,  31.f}, { -84.f, -40.f,  99.f,  55.f},
  {-176.f, -88.f, 191.f, 103.f}, {-360.f,-184.f, 375.f, 199.f},
  { -8.f,  -8.f,  23.f,  23.f}, { -24.f, -24.f,  39.f,  39.f}, { -56.f, -56.f,  71.f,  71.f},
  {-120.f,-120.f, 135.f, 135.f}, {-248.f,-248.f, 263.f, 263.f},
  { -3.f, -14.f,  18.f,  29.f}, { -14.f, -36.f,  29.f,  51.f}, { -36.f, -80.f,  51.f,  95.f},
  { -80.f,-168.f,  95.f, 183.f}, {-168.f,-344.f, 183.f, 359.f}
};

// ---------------- prep: transpose conv1 weights (512 x 9216) -> (9216 x 512) ----------------
__global__ void transpose_w_kernel(const float* __restrict__ w) {
    __shared__ float tile[32][33];
    int tx = threadIdx.x, ty = threadIdx.y;
    int kke = blockIdx.x*32 + tx;     // 0..9215
    int oc  = blockIdx.y*32 + ty;     // 0..511
    tile[ty][tx] = w[(size_t)oc*9216 + kke];
    __syncthreads();
    int okke = blockIdx.x*32 + ty;
    int ooc  = blockIdx.y*32 + tx;
    g_w2[(size_t)okke*512 + ooc] = tile[tx][ty];
}

// ---------------- prep: pack head weights [c][96] ----------------
__global__ void prep_wpad_kernel(const float* __restrict__ score_w,
                                 const float* __restrict__ bbox_w) {
    int t = blockIdx.x*256 + threadIdx.x;
    if (t >= COUT*96) return;
    int c = t / 96, o = t % 96;
    float v = 0.f;
    if (o < 30)       v = score_w[(size_t)o*512 + c];
    else if (o < 90)  v = bbox_w[(size_t)(o-30)*512 + c];
    g_wpad[t] = v;
}

// ---------------- conv1 3x3 SAME + BN + ReLU ----------------
// block: 256 threads = 16 oc-groups(x4 oc) * 16 px-groups(x6 px); tile = 64 oc x 96 px (one row)
__global__ void __launch_bounds__(256, 4) conv1_kernel(
    const float* __restrict__ in, const float* __restrict__ conv_b,
    const float* __restrict__ gamma, const float* __restrict__ beta,
    const float* __restrict__ mean, const float* __restrict__ var) {
    __shared__ float s_in[8][3][98];
    __shared__ float s_w[72][64];

    const int y   = blockIdx.x;          // output row
    const int ocb = blockIdx.y * 64;     // oc tile base
    const int tid = threadIdx.x;
    const int px_g = tid & 15;           // 0..15, 6 px each
    const int oc_g = tid >> 4;           // 0..15, 4 oc each

    float acc[4][6];
    #pragma unroll
    for (int m=0;m<4;m++)
        #pragma unroll
        for (int p=0;p<6;p++) acc[m][p]=0.f;

    for (int chunk=0; chunk<CIN/8; chunk++) {
        const int ic0 = chunk*8;
        // load weights: 72*64 floats
        #pragma unroll
        for (int r=0;r<18;r++) {
            int e = r*256 + tid;
            int ke = e >> 6, ocl = e & 63;
            s_w[ke][ocl] = g_w2[((size_t)ic0*9 + ke)*512 + ocb + ocl];
        }
        // load input: 8 ic * 3 rows * 98 cols
        for (int e=tid; e<8*3*98; e+=256) {
            int icl = e/294; int rem = e%294; int ry = rem/98; int x = rem%98 - 1;
            int gy = y + ry - 1;
            float v = 0.f;
            if (x>=0 && x<96 && gy>=0 && gy<96)
                v = in[((size_t)(ic0+icl))*NPOS + gy*96 + x];
            s_in[icl][ry][x+1] = v;
        }
        __syncthreads();
        #pragma unroll
        for (int icl=0; icl<8; icl++) {
            #pragma unroll
            for (int ky=0; ky<3; ky++) {
                float xv[8];
                #pragma unroll
                for (int q=0;q<8;q++) xv[q] = s_in[icl][ky][px_g*6 + q];
                #pragma unroll
                for (int kx=0; kx<3; kx++) {
                    float4 wv = *(const float4*)&s_w[icl*9 + ky*3 + kx][oc_g*4];
                    #pragma unroll
                    for (int p=0;p<6;p++) {
                        float iv = xv[kx+p];
                        acc[0][p] += wv.x * iv;
                        acc[1][p] += wv.y * iv;
                        acc[2][p] += wv.z * iv;
                        acc[3][p] += wv.w * iv;
                    }
                }
            }
        }
        __syncthreads();
    }
    // epilogue: BN affine + ReLU, store transposed [pos][oc]
    #pragma unroll
    for (int m=0;m<4;m++) {
        int oc = ocb + oc_g*4 + m;
        float sc = gamma[oc] / sqrtf(var[oc] + 1e-5f);
        float sh = (conv_b[oc] - mean[oc]) * sc + beta[oc];
        #pragma unroll
        for (int p=0;p<6;p++) {
            float v = acc[m][p]*sc + sh;
            v = fmaxf(v, 0.f);
            g_Xt[(size_t)(y*96 + px_g*6 + p)*512 + oc] = v;
        }
    }
}

// ---------------- heads 1x1 GEMM: 96(outs) x 9216(pos) x 512 ----------------
// block 256 threads: 32 og (3 outs each: og, og+32, og+64) x 8 pg (4 pos each); tile 96 x 32
__global__ void __launch_bounds__(256) heads_kernel(
    const float* __restrict__ score_b, const float* __restrict__ bbox_b) {
    __shared__ float sv[32][33];   // [c][pos]
    __shared__ float sw[32][96];   // [c][out]
    const int pos0 = blockIdx.x * 32;
    const int tid = threadIdx.x;
    const int og = tid & 31, pg = tid >> 5;

    float acc[3][4];
    #pragma unroll
    for (int m=0;m<3;m++)
        #pragma unroll
        for (int q=0;q<4;q++) acc[m][q]=0.f;

    for (int c0=0; c0<512; c0+=32) {
        {
            int pos_l = tid >> 5, c_l = tid & 31;
            #pragma unroll
            for (int r=0;r<4;r++)
                sv[c_l][pos_l + r*8] = g_Xt[(size_t)(pos0 + pos_l + r*8)*512 + c0 + c_l];
        }
        #pragma unroll
        for (int r=0;r<12;r++) {
            int e = r*256 + tid;
            int cc = e/96, oo = e%96;
            sw[cc][oo] = g_wpad[(size_t)(c0+cc)*96 + oo];
        }
        __syncthreads();
        #pragma unroll
        for (int c=0;c<32;c++) {
            float w0 = sw[c][og], w1 = sw[c][og+32], w2 = sw[c][og+64];
            #pragma unroll
            for (int q=0;q<4;q++) {
                float v = sv[c][pg*4 + q];
                acc[0][q] += w0*v; acc[1][q] += w1*v; acc[2][q] += w2*v;
            }
        }
        __syncthreads();
    }
    #pragma unroll
    for (int m=0;m<3;m++) {
        int o = og + m*32;
        if (o >= 90) continue;
        float b = (o < 30) ? score_b[o] : bbox_b[o-30];
        #pragma unroll
        for (int q=0;q<4;q++)
            g_dots[(size_t)(pos0 + pg*4 + q)*96 + o] = acc[m][q] + b;
    }
}

// ---------------- per-anchor: score, box transform, clip, filter, key ----------------
__global__ void proposal_kernel(const float* __restrict__ im_info) {
    int i = blockIdx.x*256 + threadIdx.x;
    if (i >= NANCH) return;
    int pos = i / NA, a = i % NA;
    int hy = pos / 96, wx = pos % 96;
    const float* dt = &g_dots[(size_t)pos*96];

    float bg = dt[a], fg = dt[15+a];
    float mx = fmaxf(bg, fg);
    float eb = expf(bg - mx), ef = expf(fg - mx);
    float score = ef / (eb + ef);

    float d0 = dt[30+4*a+0], d1 = dt[30+4*a+1], d2 = dt[30+4*a+2], d3 = dt[30+4*a+3];

    float ax1 = c_anchors[a][0] + wx*16.f;
    float ay1 = c_anchors[a][1] + hy*16.f;
    float ax2 = c_anchors[a][2] + wx*16.f;
    float ay2 = c_anchors[a][3] + hy*16.f;
    float aw = ax2 - ax1 + 1.f, ah = ay2 - ay1 + 1.f;
    float acx = ax1 + 0.5f*aw, acy = ay1 + 0.5f*ah;
    float px = d0*aw + acx, py = d1*ah + acy;
    float pw = expf(d2)*aw, ph = expf(d3)*ah;

    float imh = im_info[0], imw = im_info[1], ims = im_info[2];
    float x1 = fminf(fmaxf(px - 0.5f*pw, 0.f), imw - 1.f);
    float y1 = fminf(fmaxf(py - 0.5f*ph, 0.f), imh - 1.f);
    float x2 = fminf(fmaxf(px + 0.5f*pw - 1.f, 0.f), imw - 1.f);
    float y2 = fminf(fmaxf(py + 0.5f*ph - 1.f, 0.f), imh - 1.f);

    float ms = 16.f * ims;
    bool keep = ((x2 - x1 + 1.f) >= ms) && ((y2 - y1 + 1.f) >= ms);
    float s = keep ? score : -1.f;

    g_box[(size_t)i*4+0] = x1;
    g_box[(size_t)i*4+1] = y1;
    g_box[(size_t)i*4+2] = x2;
    g_box[(size_t)i*4+3] = y2;

    unsigned int b = __float_as_uint(s);
    unsigned int u = (b & 0x80000000u) ? ~b : (b | 0x80000000u);  // monotonic map
    g_keys[i] = ((unsigned long long)u << 32) | (unsigned int)(~(unsigned int)i);
}

// ---------------- gather top-6000 ----------------
__global__ void gather_kernel() {
    int j = blockIdx.x*256 + threadIdx.x;
    if (j >= PRE) return;
    unsigned long long k = g_keys_sorted[j];
    unsigned int idx = ~(unsigned int)(k & 0xFFFFFFFFull);
    int valid = (int)(k >> 63);  // top bit set <=> score >= 0
    float x1 = g_box[(size_t)idx*4+0], y1 = g_box[(size_t)idx*4+1];
    float x2 = g_box[(size_t)idx*4+2], y2 = g_box[(size_t)idx*4+3];
    g_bs[j*4+0]=x1; g_bs[j*4+1]=y1; g_bs[j*4+2]=x2; g_bs[j*4+3]=y2;
    g_area[j] = (x2 - x1 + 1.f) * (y2 - y1 + 1.f);
    g_valid[j] = valid;
}

// ---------------- NMS suppression bitmask: 6000 x 6000 ----------------
__global__ void nms_mask_kernel() {
    __shared__ float jb[64][4];
    __shared__ float ja[64];
    const int jw = blockIdx.x;               // word of 64 cols
    const int t  = threadIdx.x;
    const int j0 = jw*64;
    if (j0 + t < PRE) {
        jb[t][0]=g_bs[(j0+t)*4+0]; jb[t][1]=g_bs[(j0+t)*4+1];
        jb[t][2]=g_bs[(j0+t)*4+2]; jb[t][3]=g_bs[(j0+t)*4+3];
        ja[t]=g_area[j0+t];
    }
    __syncthreads();
    const int i = blockIdx.y*64 + t;
    if (i >= PRE) return;
    float x1=g_bs[i*4+0], y1=g_bs[i*4+1], x2=g_bs[i*4+2], y2=g_bs[i*4+3];
    float ar=g_area[i];
    unsigned long long bits = 0ull;
    int lim = min(64, PRE - j0);
    for (int jj=0; jj<lim; jj++) {
        float xx1 = fmaxf(x1, jb[jj][0]);
        float yy1 = fmaxf(y1, jb[jj][1]);
        float xx2 = fminf(x2, jb[jj][2]);
        float yy2 = fminf(y2, jb[jj][3]);
        float iw = fmaxf(0.f, xx2 - xx1 + 1.f);
        float ih = fmaxf(0.f, yy2 - yy1 + 1.f);
        float inter = iw*ih;
        float iou = inter / (ar + ja[jj] - inter);
        if (iou > 0.7f) bits |= (1ull << jj);
    }
    g_mask[(size_t)i*NW + jw] = bits;
}

// ---------------- sequential NMS scan (sorted order == reference argmax loop) ----------------
__global__ void nms_scan_kernel(float* __restrict__ rois) {
    __shared__ unsigned long long removed[NW];
    __shared__ int s_keep[POST];
    __shared__ int s_j;
    const int tid = threadIdx.x;
    for (int w = tid; w < NW; w += blockDim.x) {
        unsigned long long r = 0ull;
        for (int b = 0; b < 64; b++) {
            int j = w*64 + b;
            if (j >= PRE || !g_valid[j]) r |= (1ull << b);
        }
        removed[w] = r;
    }
    __syncthreads();

    int count = 0;
    for (int w = 0; w < NW; w++) {
        while (count < POST) {
            if (tid == 0) {
                unsigned long long live = ~removed[w];
                s_j = live ? (w*64 + __ffsll((long long)live) - 1) : -1;
            }
            __syncthreads();
            int j = s_j;
            __syncthreads();
            if (j < 0) break;
            if (tid == 0) s_keep[count] = j;
            count++;
            for (int ww = tid; ww < NW; ww += blockDim.x)
                removed[ww] |= g_mask[(size_t)j*NW + ww];
            __syncthreads();
        }
        if (count >= POST) break;
    }
    __syncthreads();

    for (int r = tid; r < POST; r += blockDim.x) {
        float b0=0.f,b1=0.f,b2=0.f,b3=0.f;
        if (r < count) {
            int j = s_keep[r];
            b0 = g_bs[j*4+0]; b1 = g_bs[j*4+1]; b2 = g_bs[j*4+2]; b3 = g_bs[j*4+3];
        }
        rois[r*5+0] = 0.f;
        rois[r*5+1] = b0; rois[r*5+2] = b1; rois[r*5+3] = b2; rois[r*5+4] = b3;
    }
}

// ---------------- launch ----------------
extern "C" void kernel_launch(void* const* d_in, const int* in_sizes, int n_in,
                              void* d_out, int out_size) {
    const float* features = (const float*)d_in[0];
    const float* im_info  = (const float*)d_in[1];
    const float* conv1_w  = (const float*)d_in[2];
    const float* conv1_b  = (const float*)d_in[3];
    const float* bn_gamma = (const float*)d_in[4];
    const float* bn_beta  = (const float*)d_in[5];
    const float* bn_mean  = (const float*)d_in[6];
    const float* bn_var   = (const float*)d_in[7];
    const float* score_w  = (const float*)d_in[8];
    const float* score_b  = (const float*)d_in[9];
    const float* bbox_w   = (const float*)d_in[10];
    const float* bbox_b   = (const float*)d_in[11];

    float* out = (float*)d_out;

    // 1) features passthrough
    cudaMemcpyAsync(out, features, (size_t)FEAT_ELEMS*sizeof(float),
                    cudaMemcpyDeviceToDevice, 0);

    // 2) weight prep
    transpose_w_kernel<<<dim3(9216/32, 512/32), dim3(32,32)>>>(conv1_w);
    prep_wpad_kernel<<<(COUT*96 + 255)/256, 256>>>(score_w, bbox_w);

    // 3) conv1 + BN + ReLU
    conv1_kernel<<<dim3(96, 8), 256>>>(features, conv1_b, bn_gamma, bn_beta, bn_mean, bn_var);

    // 4) heads
    heads_kernel<<<NPOS/32, 256>>>(score_b, bbox_b);

    // 5) per-anchor proposal prep
    proposal_kernel<<<(NANCH + 255)/256, 256>>>(im_info);

    // 6) sort keys descending (stable score-desc, index-asc)
    {
        void *keys_p = nullptr, *keys_sorted_p = nullptr, *temp_p = nullptr;
        cudaGetSymbolAddress(&keys_p, g_keys);
        cudaGetSymbolAddress(&keys_sorted_p, g_keys_sorted);
        cudaGetSymbolAddress(&temp_p, g_cub_temp);
        size_t tb = 0;
        cub::DeviceRadixSort::SortKeysDescending(
            nullptr, tb,
            (const unsigned long long*)keys_p, (unsigned long long*)keys_sorted_p,
            NANCH, 0, 64, (cudaStream_t)0);
        if (tb > sizeof(g_cub_temp)) tb = sizeof(g_cub_temp); // should never happen
        cub::DeviceRadixSort::SortKeysDescending(
            temp_p, tb,
            (const unsigned long long*)keys_p, (unsigned long long*)keys_sorted_p,
            NANCH, 0, 64, (cudaStream_t)0);
    }

    // 7) gather top-6000
    gather_kernel<<<(PRE + 255)/256, 256>>>();

    // 8) NMS mask
    nms_mask_kernel<<<dim3(NW, NW), 64>>>();

    // 9) NMS scan + write rois
    nms_scan_kernel<<<1, 128>>>(out + FEAT_ELEMS);

    (void)in_sizes; (void)n_in; (void)out_size;
}